// round 2
// baseline (speedup 1.0000x reference)
#include <cuda_runtime.h>
#include <math.h>

#define N_NODES 512
#define TDIM 288
#define LDIM 128
#define BBATCH 4
#define MROWS (BBATCH * N_NODES)   // 2048

// Scratch (device globals: allocation-free per harness rules)
__device__ float g_X1[MROWS * LDIM];
__device__ float g_X2[MROWS * LDIM];
__device__ float g_S1[MROWS * LDIM];
__device__ float g_S2P[MROWS * LDIM];
__device__ float g_P[BBATCH * N_NODES * N_NODES];

// ---------------------------------------------------------------------------
// Generic NT GEMM (both operands K-major): C[m][n] = act(sum_k A[m,k]*B[n,k] + bias[n])
// Two problem instances selected by blockIdx.z (fuses independent launches).
// BM=BN=64, BK=16, 256 threads, 4x4 micro-tile per thread (strided frags).
// ---------------------------------------------------------------------------
template <int LEAKY>
__global__ __launch_bounds__(256)
void gemm_stage(const float* __restrict__ Aa, const float* __restrict__ Ab, int lda,
                const float* __restrict__ Ba, const float* __restrict__ Bb, int ldb,
                const float* __restrict__ biasa, const float* __restrict__ biasb,
                float* __restrict__ Ca, float* __restrict__ Cb,
                int K, int ldc)
{
    const float* A    = blockIdx.z ? Ab    : Aa;
    const float* B    = blockIdx.z ? Bb    : Ba;
    const float* bias = blockIdx.z ? biasb : biasa;
    float*       C    = blockIdx.z ? Cb    : Ca;

    __shared__ float As[16][65];
    __shared__ float Bs[16][65];

    const int t  = threadIdx.x;
    const int tx = t & 15;
    const int ty = t >> 4;
    const int m0 = blockIdx.x * 64;
    const int n0 = blockIdx.y * 64;

    float acc[4][4] = {};

    for (int k0 = 0; k0 < K; k0 += 16) {
#pragma unroll
        for (int s = 0; s < 4; s++) {
            int e = t + s * 256;       // 0..1023
            int m = e >> 4;
            int k = e & 15;
            As[k][m] = A[(size_t)(m0 + m) * lda + k0 + k];
        }
#pragma unroll
        for (int s = 0; s < 4; s++) {
            int e = t + s * 256;
            int n = e >> 4;
            int k = e & 15;
            Bs[k][n] = B[(size_t)(n0 + n) * ldb + k0 + k];
        }
        __syncthreads();
#pragma unroll
        for (int k = 0; k < 16; k++) {
            float ra[4], rb[4];
#pragma unroll
            for (int r = 0; r < 4; r++) ra[r] = As[k][ty + 16 * r];
#pragma unroll
            for (int c = 0; c < 4; c++) rb[c] = Bs[k][tx + 16 * c];
#pragma unroll
            for (int r = 0; r < 4; r++)
#pragma unroll
                for (int c = 0; c < 4; c++)
                    acc[r][c] = fmaf(ra[r], rb[c], acc[r][c]);
        }
        __syncthreads();
    }

#pragma unroll
    for (int r = 0; r < 4; r++) {
        int m = m0 + ty + 16 * r;
#pragma unroll
        for (int c = 0; c < 4; c++) {
            int n = n0 + tx + 16 * c;
            float v = acc[r][c];
            if (bias) v += bias[n];
            if (LEAKY) v = fmaxf(v, 0.2f * v);
            C[(size_t)m * ldc + n] = v;
        }
    }
}

// ---------------------------------------------------------------------------
// Pairwise stage: for fixed b (blockIdx.z), 64x64 tile of (i,j):
//   logit = sum_l (0.6*Wb[l])*v + (0.4*Wb[l])*|v|,  v = S1[b,i,l] + S2P[b,j,l]
//   P[b,i,j] = sigmoid(logit + bb)
// smem tiles padded to 129 floats/row -> conflict-free strided-frag reads.
// ---------------------------------------------------------------------------
#define SROW 129

__global__ __launch_bounds__(256)
void pairwise_kernel(const float* __restrict__ S1, const float* __restrict__ S2P,
                     const float* __restrict__ Wb, const float* __restrict__ bb,
                     float* __restrict__ P)
{
    extern __shared__ float sm[];
    float*  s1t = sm;                       // [64][129]
    float*  s2t = sm + 64 * SROW;           // [64][129]
    float2* c12 = (float2*)(sm + 2 * 64 * SROW);  // [128]

    const int t  = threadIdx.x;
    const int tx = t & 15;
    const int ty = t >> 4;
    const int b  = blockIdx.z;
    const int i0 = blockIdx.y * 64;
    const int j0 = blockIdx.x * 64;

    if (t < 128) {
        float w = Wb[t];
        c12[t] = make_float2(0.6f * w, 0.4f * w);
    }

    const float* s1g = S1  + ((size_t)b * N_NODES + i0) * LDIM;
    const float* s2g = S2P + ((size_t)b * N_NODES + j0) * LDIM;
#pragma unroll
    for (int s = 0; s < 8; s++) {
        int f   = t + s * 256;    // float4 index, 0..2047
        int row = f >> 5;         // 0..63
        int c4  = f & 31;
        float4 v = ((const float4*)s1g)[row * 32 + c4];
        float4 w = ((const float4*)s2g)[row * 32 + c4];
        int base = row * SROW + c4 * 4;
        s1t[base + 0] = v.x; s1t[base + 1] = v.y; s1t[base + 2] = v.z; s1t[base + 3] = v.w;
        s2t[base + 0] = w.x; s2t[base + 1] = w.y; s2t[base + 2] = w.z; s2t[base + 3] = w.w;
    }
    __syncthreads();

    float acc[4][4] = {};
#pragma unroll 4
    for (int l = 0; l < LDIM; l++) {
        float2 cc = c12[l];
        float ra[4], rb[4];
#pragma unroll
        for (int r = 0; r < 4; r++) ra[r] = s1t[(ty + 16 * r) * SROW + l];
#pragma unroll
        for (int c = 0; c < 4; c++) rb[c] = s2t[(tx + 16 * c) * SROW + l];
#pragma unroll
        for (int r = 0; r < 4; r++)
#pragma unroll
            for (int c = 0; c < 4; c++) {
                float v = ra[r] + rb[c];
                acc[r][c] = fmaf(cc.y, fabsf(v), acc[r][c]);
                acc[r][c] = fmaf(cc.x, v, acc[r][c]);
            }
    }

    const float bbv = bb[0];
    float* Pb = P + (size_t)b * N_NODES * N_NODES;
#pragma unroll
    for (int r = 0; r < 4; r++) {
        int i = i0 + ty + 16 * r;
#pragma unroll
        for (int c = 0; c < 4; c++) {
            int j = j0 + tx + 16 * c;
            float z = acc[r][c] + bbv;
            Pb[(size_t)i * N_NODES + j] = 1.f / (1.f + expf(-z));
        }
    }
}

// ---------------------------------------------------------------------------
// Final: p = mean_b sigmoid -> mask diag -> clamped logit -> +logistic(noise)
//        -> sigmoid(/0.2)
// ---------------------------------------------------------------------------
__global__ __launch_bounds__(256)
void finalize_kernel(const float* __restrict__ P, const float* __restrict__ noise,
                     float* __restrict__ out)
{
    int idx = blockIdx.x * blockDim.x + threadIdx.x;
    if (idx >= N_NODES * N_NODES) return;
    int i = idx >> 9;
    int j = idx & (N_NODES - 1);
    const int PL = N_NODES * N_NODES;
    float p = 0.25f * (P[idx] + P[idx + PL] + P[idx + 2 * PL] + P[idx + 3 * PL]);
    if (i == j) p = 0.f;
    float lp = logf(p + 1e-10f) - log1pf(1e-10f - p);
    lp = fminf(fmaxf(lp, -10.f), 10.f);
    float ns = noise[idx];
    float lo = logf(ns) - log1pf(-ns);
    float z = (lp + lo) * 5.0f;   // divide by TEMPERATURE=0.2
    out[idx] = 1.f / (1.f + expf(-z));
}

// ---------------------------------------------------------------------------
extern "C" void kernel_launch(void* const* d_in, const int* in_sizes, int n_in,
                              void* d_out, int out_size)
{
    const float* x     = (const float*)d_in[0];
    const float* W1    = (const float*)d_in[1];
    const float* b1    = (const float*)d_in[2];
    const float* W2    = (const float*)d_in[3];
    const float* b2    = (const float*)d_in[4];
    const float* Wp    = (const float*)d_in[5];
    const float* bp    = (const float*)d_in[6];
    const float* Wb    = (const float*)d_in[7];
    const float* bb    = (const float*)d_in[8];
    const float* noise = (const float*)d_in[9];
    float* out = (float*)d_out;

    float *X1, *X2, *S1, *S2P, *P;
    cudaGetSymbolAddress((void**)&X1,  g_X1);
    cudaGetSymbolAddress((void**)&X2,  g_X2);
    cudaGetSymbolAddress((void**)&S1,  g_S1);
    cudaGetSymbolAddress((void**)&S2P, g_S2P);
    cudaGetSymbolAddress((void**)&P,   g_P);

    dim3 blk(256);

    // Stage 1: X1 = leaky(x@W1^T + b1), X2 = leaky(x@W2^T + b2)   (z selects)
    dim3 g1(MROWS / 64, LDIM / 64, 2);
    gemm_stage<1><<<g1, blk>>>(x, x, TDIM,
                               W1, W2, TDIM,
                               b1, b2,
                               X1, X2,
                               TDIM, LDIM);

    // Stage 2: S1 = X1@Wp_a^T (no bias), S2P = X2@Wp_b^T + bp
    dim3 g2(MROWS / 64, LDIM / 64, 2);
    gemm_stage<0><<<g2, blk>>>(X1, X2, LDIM,
                               Wp, Wp + LDIM, 2 * LDIM,
                               nullptr, bp,
                               S1, S2P,
                               LDIM, LDIM);

    // Stage 3: pairwise logits + sigmoid into per-b planes
    size_t smem = (size_t)(2 * 64 * SROW) * sizeof(float) + 128 * sizeof(float2);
    cudaFuncSetAttribute(pairwise_kernel, cudaFuncAttributeMaxDynamicSharedMemorySize,
                         (int)smem);
    dim3 g3(N_NODES / 64, N_NODES / 64, BBATCH);
    pairwise_kernel<<<g3, blk, smem>>>(S1, S2P, Wb, bb, P);

    // Stage 4: epilogue
    int tot = N_NODES * N_NODES;
    finalize_kernel<<<(tot + 255) / 256, 256>>>(P, noise, out);
}

// round 3
// speedup vs baseline: 1.0695x; 1.0695x over previous
#include <cuda_runtime.h>
#include <math.h>

#define N_NODES 512
#define TDIM 288
#define LDIM 128
#define BBATCH 4
#define MROWS (BBATCH * N_NODES)   // 2048

typedef unsigned long long u64;

// ---- packed f32x2 helpers (sm_100+) ----
__device__ __forceinline__ u64 add2(u64 a, u64 b) {
    u64 r; asm("add.rn.f32x2 %0,%1,%2;" : "=l"(r) : "l"(a), "l"(b)); return r;
}
__device__ __forceinline__ u64 fma2(u64 a, u64 b, u64 c) {
    u64 r; asm("fma.rn.f32x2 %0,%1,%2,%3;" : "=l"(r) : "l"(a), "l"(b), "l"(c)); return r;
}
__device__ __forceinline__ float lo32(u64 v) { return __uint_as_float((unsigned)(v & 0xffffffffu)); }
__device__ __forceinline__ float hi32(u64 v) { return __uint_as_float((unsigned)(v >> 32)); }
__device__ __forceinline__ u64 pack2(float x, float y) {
    return ((u64)__float_as_uint(y) << 32) | (u64)__float_as_uint(x);
}

// Scratch (device globals: allocation-free per harness rules)
__device__ float g_X1[MROWS * LDIM];
__device__ float g_X2[MROWS * LDIM];
__device__ float g_S1[MROWS * LDIM];
__device__ float g_S2P[MROWS * LDIM];
__device__ float g_P[BBATCH * N_NODES * N_NODES];

// ---------------------------------------------------------------------------
// NT GEMM (both operands K-major), packed f32x2 inner product.
// C[m][n] = act(sum_k A[m,k]*B[n,k] + bias[n]); two instances via blockIdx.z.
// BM=BN=64, BK=16, 256 threads, 4x4 micro-tile. smem layout [m][k] (pad 18).
// ---------------------------------------------------------------------------
template <int LEAKY>
__global__ __launch_bounds__(256)
void gemm_stage(const float* __restrict__ Aa, const float* __restrict__ Ab, int lda,
                const float* __restrict__ Ba, const float* __restrict__ Bb, int ldb,
                const float* __restrict__ biasa, const float* __restrict__ biasb,
                float* __restrict__ Ca, float* __restrict__ Cb,
                int K, int ldc)
{
    const float* A    = blockIdx.z ? Ab    : Aa;
    const float* B    = blockIdx.z ? Bb    : Ba;
    const float* bias = blockIdx.z ? biasb : biasa;
    float*       C    = blockIdx.z ? Cb    : Ca;

    __shared__ __align__(8) float As[64 * 18];   // [m][k], 16 k + 2 pad
    __shared__ __align__(8) float Bs[64 * 18];

    const int t  = threadIdx.x;
    const int tx = t & 15;
    const int ty = t >> 4;
    const int m0 = blockIdx.x * 64;
    const int n0 = blockIdx.y * 64;

    u64 acc[4][4] = {};

    for (int k0 = 0; k0 < K; k0 += 16) {
#pragma unroll
        for (int s = 0; s < 4; s++) {
            int e = t + s * 256;       // 0..1023
            int m = e >> 4;
            int k = e & 15;
            As[m * 18 + k] = A[(size_t)(m0 + m) * lda + k0 + k];
        }
#pragma unroll
        for (int s = 0; s < 4; s++) {
            int e = t + s * 256;
            int n = e >> 4;
            int k = e & 15;
            Bs[n * 18 + k] = B[(size_t)(n0 + n) * ldb + k0 + k];
        }
        __syncthreads();
        const u64* As2 = (const u64*)As;   // row stride 9 u64
        const u64* Bs2 = (const u64*)Bs;
#pragma unroll
        for (int kk = 0; kk < 8; kk++) {
            u64 ra[4], rb[4];
#pragma unroll
            for (int r = 0; r < 4; r++) ra[r] = As2[(ty + 16 * r) * 9 + kk];
#pragma unroll
            for (int c = 0; c < 4; c++) rb[c] = Bs2[(tx + 16 * c) * 9 + kk];
#pragma unroll
            for (int r = 0; r < 4; r++)
#pragma unroll
                for (int c = 0; c < 4; c++)
                    acc[r][c] = fma2(ra[r], rb[c], acc[r][c]);
        }
        __syncthreads();
    }

#pragma unroll
    for (int r = 0; r < 4; r++) {
        int m = m0 + ty + 16 * r;
#pragma unroll
        for (int c = 0; c < 4; c++) {
            int n = n0 + tx + 16 * c;
            float v = lo32(acc[r][c]) + hi32(acc[r][c]);
            if (bias) v += bias[n];
            if (LEAKY) v = fmaxf(v, 0.2f * v);
            C[(size_t)m * ldc + n] = v;
        }
    }
}

// ---------------------------------------------------------------------------
// Pairwise stage (separable form):
//   logit[i,j] = A_i + B_j + bb + sum_l (0.4*Wb_l)*|S1[i,l]+S2P[j,l]|
//   with A_i = sum_l (0.6*Wb_l)*S1[i,l],  B_j = sum_l (0.6*Wb_l)*S2P[j,l]
//   P[b,i,j] = sigmoid(logit)
// 64x64 tile per block, 4x4 micro-tile, packed f32x2 inner loop (64 steps).
// ---------------------------------------------------------------------------
#define SROW2 65   // u64 per row (64 + 1 pad)

__global__ __launch_bounds__(256)
void pairwise_kernel(const float* __restrict__ S1, const float* __restrict__ S2P,
                     const float* __restrict__ Wb, const float* __restrict__ bb,
                     float* __restrict__ P)
{
    extern __shared__ u64 sm[];
    u64*   s1t   = sm;                       // [64][65] u64
    u64*   s2t   = sm + 64 * SROW2;
    u64*   c1    = sm + 2 * 64 * SROW2;      // 64 (0.6*Wb packed)
    u64*   c2    = c1 + 64;                  // 64 (0.4*Wb packed)
    float* rowAB = (float*)(c2 + 64);        // [128]: A rows then B rows

    const int t  = threadIdx.x;
    const int tx = t & 15;
    const int ty = t >> 4;
    const int b  = blockIdx.z;
    const int i0 = blockIdx.y * 64;
    const int j0 = blockIdx.x * 64;

    if (t < 64) {
        float2 w = ((const float2*)Wb)[t];
        c1[t] = pack2(0.6f * w.x, 0.6f * w.y);
        c2[t] = pack2(0.4f * w.x, 0.4f * w.y);
    }

    const float* s1g = S1  + ((size_t)b * N_NODES + i0) * LDIM;
    const float* s2g = S2P + ((size_t)b * N_NODES + j0) * LDIM;
    float2* s1f = (float2*)s1t;
    float2* s2f = (float2*)s2t;
#pragma unroll
    for (int s = 0; s < 8; s++) {
        int f   = t + s * 256;    // float4 index, 0..2047
        int row = f >> 5;         // 0..63 (32 float4 per row)
        int c4  = f & 31;
        float4 v = ((const float4*)s1g)[row * 32 + c4];
        float4 w = ((const float4*)s2g)[row * 32 + c4];
        int base = row * SROW2 + c4 * 2;
        s1f[base]     = make_float2(v.x, v.y);
        s1f[base + 1] = make_float2(v.z, v.w);
        s2f[base]     = make_float2(w.x, w.y);
        s2f[base + 1] = make_float2(w.z, w.w);
    }
    __syncthreads();

    // Per-row separable dot products: 2 threads per row, 32 packed each.
    {
        int row  = t >> 1;
        int half = t & 1;
        const u64* src = (row < 64) ? (s1t + row * SROW2)
                                    : (s2t + (row - 64) * SROW2);
        u64 a = 0;
#pragma unroll
        for (int q = 0; q < 32; q++)
            a = fma2(c1[half * 32 + q], src[half * 32 + q], a);
        float s = lo32(a) + hi32(a);
        s += __shfl_xor_sync(0xffffffffu, s, 1);
        if (half == 0) rowAB[row] = s;
    }
    __syncthreads();

    u64 acc[4][4] = {};
    const u64 MASK = 0x7fffffff7fffffffULL;
#pragma unroll 2
    for (int kk = 0; kk < 64; kk++) {
        u64 cw = c2[kk];
        u64 ra[4], rb[4];
#pragma unroll
        for (int r = 0; r < 4; r++) ra[r] = s1t[(ty + 16 * r) * SROW2 + kk];
#pragma unroll
        for (int c = 0; c < 4; c++) rb[c] = s2t[(tx + 16 * c) * SROW2 + kk];
#pragma unroll
        for (int r = 0; r < 4; r++)
#pragma unroll
            for (int c = 0; c < 4; c++) {
                u64 v = add2(ra[r], rb[c]);
                acc[r][c] = fma2(cw, v & MASK, acc[r][c]);
            }
    }

    const float bbv = bb[0];
    float* Pb = P + (size_t)b * N_NODES * N_NODES;
#pragma unroll
    for (int r = 0; r < 4; r++) {
        int i = i0 + ty + 16 * r;
        float ai = rowAB[ty + 16 * r];
#pragma unroll
        for (int c = 0; c < 4; c++) {
            int j = j0 + tx + 16 * c;
            float z = lo32(acc[r][c]) + hi32(acc[r][c])
                    + ai + rowAB[64 + tx + 16 * c] + bbv;
            Pb[(size_t)i * N_NODES + j] = 1.f / (1.f + __expf(-z));
        }
    }
}

// ---------------------------------------------------------------------------
// Final: p = mean_b P -> mask diag -> clamped logit -> +logistic(noise)
//        -> sigmoid(/0.2).  4 elements per thread (float4), fast intrinsics.
// ---------------------------------------------------------------------------
__global__ __launch_bounds__(256)
void finalize_kernel(const float* __restrict__ P, const float* __restrict__ noise,
                     float* __restrict__ out)
{
    int q = blockIdx.x * blockDim.x + threadIdx.x;   // float4 index
    const int PL4 = N_NODES * N_NODES / 4;
    if (q >= PL4) return;
    float4 p0 = ((const float4*)P)[q];
    float4 p1 = ((const float4*)P)[q + PL4];
    float4 p2 = ((const float4*)P)[q + 2 * PL4];
    float4 p3 = ((const float4*)P)[q + 3 * PL4];
    float4 ns = ((const float4*)noise)[q];

    int idx0 = q * 4;
    int i = idx0 >> 9;
    int jbase = idx0 & (N_NODES - 1);

    float pv[4] = { 0.25f * (p0.x + p1.x + p2.x + p3.x),
                    0.25f * (p0.y + p1.y + p2.y + p3.y),
                    0.25f * (p0.z + p1.z + p2.z + p3.z),
                    0.25f * (p0.w + p1.w + p2.w + p3.w) };
    float nv[4] = { ns.x, ns.y, ns.z, ns.w };
    float4 o;
    float* op = (float*)&o;
#pragma unroll
    for (int e = 0; e < 4; e++) {
        float p = pv[e];
        if (i == jbase + e) p = 0.f;
        float lp = __logf(p + 1e-10f) - __logf(1.0f + (1e-10f - p));
        lp = fminf(fmaxf(lp, -10.f), 10.f);
        float lo = __logf(nv[e]) - __logf(1.0f - nv[e]);
        float z = (lp + lo) * 5.0f;     // / TEMPERATURE (0.2)
        op[e] = 1.f / (1.f + __expf(-z));
    }
    ((float4*)out)[q] = o;
}

// ---------------------------------------------------------------------------
extern "C" void kernel_launch(void* const* d_in, const int* in_sizes, int n_in,
                              void* d_out, int out_size)
{
    const float* x     = (const float*)d_in[0];
    const float* W1    = (const float*)d_in[1];
    const float* b1    = (const float*)d_in[2];
    const float* W2    = (const float*)d_in[3];
    const float* b2    = (const float*)d_in[4];
    const float* Wp    = (const float*)d_in[5];
    const float* bp    = (const float*)d_in[6];
    const float* Wb    = (const float*)d_in[7];
    const float* bb    = (const float*)d_in[8];
    const float* noise = (const float*)d_in[9];
    float* out = (float*)d_out;

    float *X1, *X2, *S1, *S2P, *P;
    cudaGetSymbolAddress((void**)&X1,  g_X1);
    cudaGetSymbolAddress((void**)&X2,  g_X2);
    cudaGetSymbolAddress((void**)&S1,  g_S1);
    cudaGetSymbolAddress((void**)&S2P, g_S2P);
    cudaGetSymbolAddress((void**)&P,   g_P);

    dim3 blk(256);

    // Stage 1: X1 = leaky(x@W1^T + b1), X2 = leaky(x@W2^T + b2)
    dim3 g1(MROWS / 64, LDIM / 64, 2);
    gemm_stage<1><<<g1, blk>>>(x, x, TDIM,
                               W1, W2, TDIM,
                               b1, b2,
                               X1, X2,
                               TDIM, LDIM);

    // Stage 2: S1 = X1@Wp_a^T (no bias), S2P = X2@Wp_b^T + bp
    dim3 g2(MROWS / 64, LDIM / 64, 2);
    gemm_stage<0><<<g2, blk>>>(X1, X2, LDIM,
                               Wp, Wp + LDIM, 2 * LDIM,
                               nullptr, bp,
                               S1, S2P,
                               LDIM, LDIM);

    // Stage 3: pairwise logits + sigmoid into per-b planes
    size_t smem = (size_t)(2 * 64 * SROW2 + 128) * sizeof(u64) + 128 * sizeof(float);
    cudaFuncSetAttribute(pairwise_kernel, cudaFuncAttributeMaxDynamicSharedMemorySize,
                         (int)smem);
    dim3 g3(N_NODES / 64, N_NODES / 64, BBATCH);
    pairwise_kernel<<<g3, blk, smem>>>(S1, S2P, Wb, bb, P);

    // Stage 4: epilogue
    int tot4 = N_NODES * N_NODES / 4;
    finalize_kernel<<<(tot4 + 255) / 256, 256>>>(P, noise, out);
}

// round 4
// speedup vs baseline: 1.2420x; 1.1614x over previous
#include <cuda_runtime.h>
#include <math.h>

#define N_NODES 512
#define TDIM 288
#define LDIM 128
#define BBATCH 4
#define MROWS (BBATCH * N_NODES)   // 2048

typedef unsigned long long u64;

// ---- packed f32x2 helpers (sm_100+) ----
__device__ __forceinline__ u64 add2(u64 a, u64 b) {
    u64 r; asm("add.rn.f32x2 %0,%1,%2;" : "=l"(r) : "l"(a), "l"(b)); return r;
}
__device__ __forceinline__ u64 fma2(u64 a, u64 b, u64 c) {
    u64 r; asm("fma.rn.f32x2 %0,%1,%2,%3;" : "=l"(r) : "l"(a), "l"(b), "l"(c)); return r;
}
__device__ __forceinline__ float lo32(u64 v) { return __uint_as_float((unsigned)(v & 0xffffffffu)); }
__device__ __forceinline__ float hi32(u64 v) { return __uint_as_float((unsigned)(v >> 32)); }
__device__ __forceinline__ u64 pack2(float x, float y) {
    return ((u64)__float_as_uint(y) << 32) | (u64)__float_as_uint(x);
}

// Scratch (device globals: allocation-free per harness rules)
__device__ float g_X1[MROWS * LDIM];
__device__ float g_X2[MROWS * LDIM];
__device__ float g_S1[MROWS * LDIM];
__device__ float g_S2P[MROWS * LDIM];

// ---------------------------------------------------------------------------
// NT GEMM, double-buffered smem, packed f32x2 inner product.
// C[m][n] = act(sum_k A[m,k]*B[n,k] + bias[n]); two instances via blockIdx.z.
// BM=BN=64, BK=16, 256 threads, 4x4 micro-tile. smem [m][k] pad 18 floats.
// ---------------------------------------------------------------------------
template <int LEAKY>
__global__ __launch_bounds__(256)
void gemm_stage(const float* __restrict__ Aa, const float* __restrict__ Ab, int lda,
                const float* __restrict__ Ba, const float* __restrict__ Bb, int ldb,
                const float* __restrict__ biasa, const float* __restrict__ biasb,
                float* __restrict__ Ca, float* __restrict__ Cb,
                int K, int ldc)
{
    const float* A    = blockIdx.z ? Ab    : Aa;
    const float* B    = blockIdx.z ? Bb    : Ba;
    const float* bias = blockIdx.z ? biasb : biasa;
    float*       C    = blockIdx.z ? Cb    : Ca;

    __shared__ __align__(16) float As[2][64 * 18];
    __shared__ __align__(16) float Bs[2][64 * 18];

    const int t  = threadIdx.x;
    const int tx = t & 15;
    const int ty = t >> 4;
    const int m0 = blockIdx.x * 64;
    const int n0 = blockIdx.y * 64;

    // float4 load mapping: each thread loads one float4 per side per tile.
    const int lm = t >> 2;          // row 0..63
    const int lk = (t & 3) * 4;     // k offset 0,4,8,12

    u64 acc[4][4] = {};
    float4 pa, pb;

    // prologue: tile 0
    pa = *(const float4*)&A[(size_t)(m0 + lm) * lda + lk];
    pb = *(const float4*)&B[(size_t)(n0 + lm) * ldb + lk];
    {
        float* d = &As[0][lm * 18 + lk];
        d[0] = pa.x; d[1] = pa.y; d[2] = pa.z; d[3] = pa.w;
        float* e = &Bs[0][lm * 18 + lk];
        e[0] = pb.x; e[1] = pb.y; e[2] = pb.z; e[3] = pb.w;
    }
    __syncthreads();

    const int nt = K / 16;
    for (int ti = 0; ti < nt; ti++) {
        int cur = ti & 1;
        if (ti + 1 < nt) {
            int k0 = (ti + 1) * 16;
            pa = *(const float4*)&A[(size_t)(m0 + lm) * lda + k0 + lk];
            pb = *(const float4*)&B[(size_t)(n0 + lm) * ldb + k0 + lk];
        }
        const u64* As2 = (const u64*)As[cur];   // row stride 9 u64
        const u64* Bs2 = (const u64*)Bs[cur];
#pragma unroll
        for (int kk = 0; kk < 8; kk++) {
            u64 ra[4], rb[4];
#pragma unroll
            for (int r = 0; r < 4; r++) ra[r] = As2[(ty + 16 * r) * 9 + kk];
#pragma unroll
            for (int c = 0; c < 4; c++) rb[c] = Bs2[(tx + 16 * c) * 9 + kk];
#pragma unroll
            for (int r = 0; r < 4; r++)
#pragma unroll
                for (int c = 0; c < 4; c++)
                    acc[r][c] = fma2(ra[r], rb[c], acc[r][c]);
        }
        if (ti + 1 < nt) {
            int nx = cur ^ 1;
            float* d = &As[nx][lm * 18 + lk];
            d[0] = pa.x; d[1] = pa.y; d[2] = pa.z; d[3] = pa.w;
            float* e = &Bs[nx][lm * 18 + lk];
            e[0] = pb.x; e[1] = pb.y; e[2] = pb.z; e[3] = pb.w;
        }
        __syncthreads();
    }

#pragma unroll
    for (int r = 0; r < 4; r++) {
        int m = m0 + ty + 16 * r;
#pragma unroll
        for (int c = 0; c < 4; c++) {
            int n = n0 + tx + 16 * c;
            float v = lo32(acc[r][c]) + hi32(acc[r][c]);
            if (bias) v += bias[n];
            if (LEAKY) v = fmaxf(v, 0.2f * v);
            C[(size_t)m * ldc + n] = v;
        }
    }
}

// ---------------------------------------------------------------------------
// Fused pairwise + finalize.
// Each block: 64x32 (i,j) tile, ALL 4 batch planes (128 threads per plane).
//   logit[b,i,j] = A_bi + B_bj + bb + sum_l (0.4 Wb_l)|S1[b,i,l]+S2P[b,j,l]|
//   sig = sigmoid(logit); p = mean_b sig; diag mask; clamped logit;
//   + logistic(noise); sigmoid(/0.2) -> out. No intermediate global buffers.
// 512 threads, 4x4 micro-tile per thread. l packed into u64 (64 kk steps).
// ---------------------------------------------------------------------------
#define SR2 65   // u64 per row (64 + 1 pad)
// smem (u64 units):
//   s1t: 4*64*SR2 = 16640        (also aliased as red[] in phase 2)
//   s2t: 4*32*SR2 = 8320     @ 16640
//   c1 : 64                  @ 24960
//   c2 : 64                  @ 25024
//   rowA: 256 f, rowB: 128 f @ 25088 (as floats @ 50176)
#define SM_S2   16640
#define SM_C1   24960
#define SM_C2   25024
#define SM_ROWF 50176           // float index of rowA
#define SM_U64_TOTAL 25280      // 202,240 bytes

__global__ __launch_bounds__(512)
void pairwise_final_kernel(const float* __restrict__ S1, const float* __restrict__ S2P,
                           const float* __restrict__ Wb, const float* __restrict__ bb,
                           const float* __restrict__ noise, float* __restrict__ out)
{
    extern __shared__ __align__(16) u64 sm[];
    u64*   s1t  = sm;
    u64*   s2t  = sm + SM_S2;
    u64*   c1   = sm + SM_C1;
    u64*   c2   = sm + SM_C2;
    float* rowA = ((float*)sm) + SM_ROWF;        // [4][64]
    float* rowB = rowA + 256;                    // [4][32]
    float* red  = (float*)sm;                    // aliased over s1t after main loop

    const int t  = threadIdx.x;
    const int b  = t >> 7;          // 0..3
    const int tb = t & 127;
    const int tx = tb & 7;          // j micro col 0..7
    const int ty = tb >> 3;         // i micro row 0..15
    const int i0 = blockIdx.y * 64;
    const int j0 = blockIdx.x * 32;

    if (t < 64) {
        float2 w = ((const float2*)Wb)[t];
        c1[t] = pack2(0.6f * w.x, 0.6f * w.y);
        c2[t] = pack2(0.4f * w.x, 0.4f * w.y);
    }

    // ---- load tiles: s1 = 4b x 64 rows, s2 = 4b x 32 rows (128 floats each)
    const float4* S1v = (const float4*)S1;
    const float4* S2v = (const float4*)S2P;
#pragma unroll
    for (int s = 0; s < 16; s++) {
        int f   = t + s * 512;          // 0..8191
        int bb_ = f >> 11;
        int rem = f & 2047;
        int row = rem >> 5;
        int c4  = rem & 31;
        float4 v = S1v[((size_t)bb_ * N_NODES + i0 + row) * 32 + c4];
        float2* d = (float2*)&s1t[(bb_ * 64 + row) * SR2 + c4 * 2];
        d[0] = make_float2(v.x, v.y);
        d[1] = make_float2(v.z, v.w);
    }
#pragma unroll
    for (int s = 0; s < 8; s++) {
        int f   = t + s * 512;          // 0..4095
        int bb_ = f >> 10;
        int rem = f & 1023;
        int row = rem >> 5;
        int c4  = rem & 31;
        float4 v = S2v[((size_t)bb_ * N_NODES + j0 + row) * 32 + c4];
        float2* d = (float2*)&s2t[(bb_ * 32 + row) * SR2 + c4 * 2];
        d[0] = make_float2(v.x, v.y);
        d[1] = make_float2(v.z, v.w);
    }
    __syncthreads();

    // ---- separable linear parts: rowA[b][i], rowB[b][j]
    if (t < 256) {
        const u64* src = s1t + t * SR2;         // t = b*64+row
        u64 a0 = 0, a1 = 0;
#pragma unroll
        for (int q = 0; q < 64; q += 2) {
            a0 = fma2(c1[q],     src[q],     a0);
            a1 = fma2(c1[q + 1], src[q + 1], a1);
        }
        rowA[t] = lo32(a0) + hi32(a0) + lo32(a1) + hi32(a1);
    } else if (t < 384) {
        int r = t - 256;                        // b*32+row
        const u64* src = s2t + r * SR2;
        u64 a0 = 0, a1 = 0;
#pragma unroll
        for (int q = 0; q < 64; q += 2) {
            a0 = fma2(c1[q],     src[q],     a0);
            a1 = fma2(c1[q + 1], src[q + 1], a1);
        }
        rowB[r] = lo32(a0) + hi32(a0) + lo32(a1) + hi32(a1);
    }
    __syncthreads();

    // ---- main loop
    u64 acc[4][4] = {};
    const u64 MASK = 0x7fffffff7fffffffULL;
    const u64* s1b = s1t + b * 64 * SR2;
    const u64* s2b = s2t + b * 32 * SR2;
#pragma unroll 2
    for (int kk = 0; kk < 64; kk++) {
        u64 cw = c2[kk];
        u64 ra[4], rb[4];
#pragma unroll
        for (int r = 0; r < 4; r++) ra[r] = s1b[(ty + 16 * r) * SR2 + kk];
#pragma unroll
        for (int c = 0; c < 4; c++) rb[c] = s2b[(tx + 8 * c) * SR2 + kk];
#pragma unroll
        for (int r = 0; r < 4; r++)
#pragma unroll
            for (int c = 0; c < 4; c++) {
                u64 v = add2(ra[r], rb[c]);
                acc[r][c] = fma2(cw, v & MASK, acc[r][c]);
            }
    }

    // ---- sigmoid per plane
    const float bbv = bb[0];
    float sig[4][4];
#pragma unroll
    for (int r = 0; r < 4; r++) {
        float ai = rowA[b * 64 + ty + 16 * r];
#pragma unroll
        for (int c = 0; c < 4; c++) {
            float z = lo32(acc[r][c]) + hi32(acc[r][c])
                    + ai + rowB[b * 32 + tx + 8 * c] + bbv;
            sig[r][c] = 1.f / (1.f + __expf(-z));
        }
    }
    __syncthreads();            // everyone done reading s1t/s2t

    // ---- write per-plane sigmoids to red[b][tb][r*4+c]
#pragma unroll
    for (int r = 0; r < 4; r++)
#pragma unroll
        for (int c = 0; c < 4; c++)
            red[(b * 128 + tb) * 16 + r * 4 + c] = sig[r][c];
    __syncthreads();

    // ---- phase 2: mean over b + epilogue; 4 outputs per thread
#pragma unroll
    for (int e = 0; e < 4; e++) {
        int o = t * 4 + e;              // 0..2047
        int i = o >> 5;                 // 0..63
        int j = o & 31;                 // 0..31
        int ty2 = i & 15, r2 = i >> 4;
        int tx2 = j & 7,  c2_ = j >> 3;
        int base = (ty2 * 8 + tx2) * 16 + r2 * 4 + c2_;
        float p = 0.25f * (red[base] + red[2048 + base]
                         + red[4096 + base] + red[6144 + base]);
        int gi = i0 + i, gj = j0 + j;
        if (gi == gj) p = 0.f;
        float lp = __logf(p + 1e-10f) - __logf(1.0f + (1e-10f - p));
        lp = fminf(fmaxf(lp, -10.f), 10.f);
        float ns = noise[(size_t)gi * N_NODES + gj];
        float lo = __logf(ns) - __logf(1.0f - ns);
        float z = (lp + lo) * 5.0f;     // / TEMPERATURE (0.2)
        out[(size_t)gi * N_NODES + gj] = 1.f / (1.f + __expf(-z));
    }
}

// ---------------------------------------------------------------------------
extern "C" void kernel_launch(void* const* d_in, const int* in_sizes, int n_in,
                              void* d_out, int out_size)
{
    const float* x     = (const float*)d_in[0];
    const float* W1    = (const float*)d_in[1];
    const float* b1    = (const float*)d_in[2];
    const float* W2    = (const float*)d_in[3];
    const float* b2    = (const float*)d_in[4];
    const float* Wp    = (const float*)d_in[5];
    const float* bp    = (const float*)d_in[6];
    const float* Wb    = (const float*)d_in[7];
    const float* bb    = (const float*)d_in[8];
    const float* noise = (const float*)d_in[9];
    float* out = (float*)d_out;

    float *X1, *X2, *S1, *S2P;
    cudaGetSymbolAddress((void**)&X1,  g_X1);
    cudaGetSymbolAddress((void**)&X2,  g_X2);
    cudaGetSymbolAddress((void**)&S1,  g_S1);
    cudaGetSymbolAddress((void**)&S2P, g_S2P);

    dim3 blk(256);

    // Stage 1: X1 = leaky(x@W1^T + b1), X2 = leaky(x@W2^T + b2)
    dim3 g1(MROWS / 64, LDIM / 64, 2);
    gemm_stage<1><<<g1, blk>>>(x, x, TDIM,
                               W1, W2, TDIM,
                               b1, b2,
                               X1, X2,
                               TDIM, LDIM);

    // Stage 2: S1 = X1@Wp_a^T (no bias), S2P = X2@Wp_b^T + bp
    dim3 g2(MROWS / 64, LDIM / 64, 2);
    gemm_stage<0><<<g2, blk>>>(X1, X2, LDIM,
                               Wp, Wp + LDIM, 2 * LDIM,
                               nullptr, bp,
                               S1, S2P,
                               LDIM, LDIM);

    // Stage 3: fused pairwise + finalize, writes out directly
    size_t smem = (size_t)SM_U64_TOTAL * sizeof(u64);
    cudaFuncSetAttribute(pairwise_final_kernel,
                         cudaFuncAttributeMaxDynamicSharedMemorySize, (int)smem);
    dim3 g3(N_NODES / 32, N_NODES / 64);   // 16 x 8 = 128 blocks
    pairwise_final_kernel<<<g3, dim3(512), smem>>>(S1, S2P, Wb, bb, noise, out);
}

// round 6
// speedup vs baseline: 1.2854x; 1.0350x over previous
#include <cuda_runtime.h>
#include <math.h>

#define N_NODES 512
#define TDIM 288
#define LDIM 128
#define BBATCH 4
#define MROWS (BBATCH * N_NODES)   // 2048

typedef unsigned long long u64;
typedef unsigned int u32;

// ---- packed f32x2 helpers (sm_100+) ----
__device__ __forceinline__ u64 add2(u64 a, u64 b) {
    u64 r; asm("add.rn.f32x2 %0,%1,%2;" : "=l"(r) : "l"(a), "l"(b)); return r;
}
__device__ __forceinline__ u64 fma2(u64 a, u64 b, u64 c) {
    u64 r; asm("fma.rn.f32x2 %0,%1,%2,%3;" : "=l"(r) : "l"(a), "l"(b), "l"(c)); return r;
}
__device__ __forceinline__ float lo32(u64 v) { return __uint_as_float((unsigned)(v & 0xffffffffu)); }
__device__ __forceinline__ float hi32(u64 v) { return __uint_as_float((unsigned)(v >> 32)); }
__device__ __forceinline__ u64 pack2(float x, float y) {
    return ((u64)__float_as_uint(y) << 32) | (u64)__float_as_uint(x);
}

// ---- tf32 helpers ----
// NOTE: cvt.rna.tf32.f32 requires a .b32 destination register ("=r"), the
// result bit-pattern is a valid fp32 with truncated mantissa.
__device__ __forceinline__ float to_tf32(float v) {
    u32 r; asm("cvt.rna.tf32.f32 %0,%1;" : "=r"(r) : "f"(v));
    return __uint_as_float(r);
}
__device__ __forceinline__ void mma_tf32(float* d, const u32* a, const u32* b) {
    asm("mma.sync.aligned.m16n8k8.row.col.f32.tf32.tf32.f32 "
        "{%0,%1,%2,%3}, {%4,%5,%6,%7}, {%8,%9}, {%0,%1,%2,%3};"
        : "+f"(d[0]), "+f"(d[1]), "+f"(d[2]), "+f"(d[3])
        : "r"(a[0]), "r"(a[1]), "r"(a[2]), "r"(a[3]), "r"(b[0]), "r"(b[1]));
}

// Scratch (device globals: allocation-free per harness rules)
__device__ float g_X1[MROWS * LDIM];
__device__ float g_X2[MROWS * LDIM];
__device__ float g_S1[MROWS * LDIM];
__device__ float g_S2P[MROWS * LDIM];

// ---------------------------------------------------------------------------
// 3xTF32 mma GEMM core. Block: 256 threads = 8 warps (2 m x 4 n).
// Tile 64m x 64n, K-chunk 32 (smem hi/lo tiles, pad 36 floats/row).
// Frags per warp: 32m x 16n via m16n8k8 (2 mfrag x 2 nfrag), 3 mma per pair.
// ---------------------------------------------------------------------------
#define SPAD 36

struct Frags {
    float acc[2][2][4];
};

__device__ __forceinline__ void split_store(float* H, float* L, int idx4, float4 v) {
    float4 h, l;
    h.x = to_tf32(v.x); l.x = to_tf32(v.x - h.x);
    h.y = to_tf32(v.y); l.y = to_tf32(v.y - h.y);
    h.z = to_tf32(v.z); l.z = to_tf32(v.z - h.z);
    h.w = to_tf32(v.w); l.w = to_tf32(v.w - h.w);
    *(float4*)(H + idx4) = h;
    *(float4*)(L + idx4) = l;
}

__device__ __forceinline__ void mma_chunk(Frags& F, const float* Ah, const float* Al,
                                          const float* Bh, const float* Bl,
                                          int wm, int wn, int gid, int ctid) {
    const u32* AhU = (const u32*)Ah; const u32* AlU = (const u32*)Al;
    const u32* BhU = (const u32*)Bh; const u32* BlU = (const u32*)Bl;
#pragma unroll
    for (int kk = 0; kk < 4; kk++) {
        int k8 = kk * 8;
        u32 ah[2][4], al[2][4], bh[2][2], bl[2][2];
#pragma unroll
        for (int mf = 0; mf < 2; mf++) {
            int r = wm * 32 + mf * 16 + gid;
            ah[mf][0] = AhU[r * SPAD + k8 + ctid];
            ah[mf][1] = AhU[(r + 8) * SPAD + k8 + ctid];
            ah[mf][2] = AhU[r * SPAD + k8 + ctid + 4];
            ah[mf][3] = AhU[(r + 8) * SPAD + k8 + ctid + 4];
            al[mf][0] = AlU[r * SPAD + k8 + ctid];
            al[mf][1] = AlU[(r + 8) * SPAD + k8 + ctid];
            al[mf][2] = AlU[r * SPAD + k8 + ctid + 4];
            al[mf][3] = AlU[(r + 8) * SPAD + k8 + ctid + 4];
        }
#pragma unroll
        for (int nf = 0; nf < 2; nf++) {
            int r = wn * 16 + nf * 8 + gid;
            bh[nf][0] = BhU[r * SPAD + k8 + ctid];
            bh[nf][1] = BhU[r * SPAD + k8 + ctid + 4];
            bl[nf][0] = BlU[r * SPAD + k8 + ctid];
            bl[nf][1] = BlU[r * SPAD + k8 + ctid + 4];
        }
#pragma unroll
        for (int mf = 0; mf < 2; mf++)
#pragma unroll
            for (int nf = 0; nf < 2; nf++) {
                mma_tf32(F.acc[mf][nf], ah[mf], bh[nf]);
                mma_tf32(F.acc[mf][nf], ah[mf], bl[nf]);
                mma_tf32(F.acc[mf][nf], al[mf], bh[nf]);
            }
    }
}

// ---------------------------------------------------------------------------
// Stage 1: [X1|X2](2048 x 256) = leaky(x(2048x288) @ [W1;W2]^T + [b1;b2])
// grid (32, 4); block n-range is entirely within X1 or X2 (64-wide).
// ---------------------------------------------------------------------------
__global__ __launch_bounds__(256)
void stage1_mma(const float* __restrict__ x,
                const float* __restrict__ W1, const float* __restrict__ W2,
                const float* __restrict__ b1, const float* __restrict__ b2,
                float* __restrict__ X1, float* __restrict__ X2)
{
    __shared__ __align__(16) float Ah[64 * SPAD], Al[64 * SPAD];
    __shared__ __align__(16) float Bh[64 * SPAD], Bl[64 * SPAD];

    const int t = threadIdx.x;
    const int lane = t & 31, warp = t >> 5;
    const int wm = warp >> 2, wn = warp & 3;
    const int gid = lane >> 2, ctid = lane & 3;
    const int m0 = blockIdx.x * 64;
    const int n0 = blockIdx.y * 64;

    const int lrow = t >> 2;          // 0..63
    const int lc8  = (t & 3) * 8;     // 0,8,16,24
    const float* wrow = (n0 + lrow) < 128 ? W1 + (size_t)(n0 + lrow) * TDIM
                                          : W2 + (size_t)(n0 + lrow - 128) * TDIM;
    const float* arow = x + (size_t)(m0 + lrow) * TDIM;

    Frags F;
#pragma unroll
    for (int mf = 0; mf < 2; mf++)
#pragma unroll
        for (int nf = 0; nf < 2; nf++)
#pragma unroll
            for (int e = 0; e < 4; e++) F.acc[mf][nf][e] = 0.f;

    for (int kc = 0; kc < TDIM; kc += 32) {
        split_store(Ah, Al, lrow * SPAD + lc8,     *(const float4*)(arow + kc + lc8));
        split_store(Ah, Al, lrow * SPAD + lc8 + 4, *(const float4*)(arow + kc + lc8 + 4));
        split_store(Bh, Bl, lrow * SPAD + lc8,     *(const float4*)(wrow + kc + lc8));
        split_store(Bh, Bl, lrow * SPAD + lc8 + 4, *(const float4*)(wrow + kc + lc8 + 4));
        __syncthreads();
        mma_chunk(F, Ah, Al, Bh, Bl, wm, wn, gid, ctid);
        __syncthreads();
    }

    // epilogue: bias + leaky -> X1/X2
    const int half = (n0 < 128);
    float* OUT = half ? X1 : X2;
    const float* bias = half ? b1 : b2;
    const int nloc0 = half ? n0 : n0 - 128;
#pragma unroll
    for (int mf = 0; mf < 2; mf++) {
        int row = m0 + wm * 32 + mf * 16 + gid;
#pragma unroll
        for (int nf = 0; nf < 2; nf++) {
            int col = nloc0 + wn * 16 + nf * 8 + 2 * ctid;
            float v0 = F.acc[mf][nf][0] + bias[col];
            float v1 = F.acc[mf][nf][1] + bias[col + 1];
            float v2 = F.acc[mf][nf][2] + bias[col];
            float v3 = F.acc[mf][nf][3] + bias[col + 1];
            v0 = fmaxf(v0, 0.2f * v0); v1 = fmaxf(v1, 0.2f * v1);
            v2 = fmaxf(v2, 0.2f * v2); v3 = fmaxf(v3, 0.2f * v3);
            *(float2*)&OUT[(size_t)row * LDIM + col]       = make_float2(v0, v1);
            *(float2*)&OUT[(size_t)(row + 8) * LDIM + col] = make_float2(v2, v3);
        }
    }
}

// ---------------------------------------------------------------------------
// Stage 2: z=0: S1 = X1 @ Wp[:, :128]^T ;  z=1: S2P = X2 @ Wp[:,128:]^T + bp
// grid (32, 2, 2).
// ---------------------------------------------------------------------------
__global__ __launch_bounds__(256)
void stage2_mma(const float* __restrict__ X1, const float* __restrict__ X2,
                const float* __restrict__ Wp, const float* __restrict__ bp,
                float* __restrict__ S1, float* __restrict__ S2P)
{
    __shared__ __align__(16) float Ah[64 * SPAD], Al[64 * SPAD];
    __shared__ __align__(16) float Bh[64 * SPAD], Bl[64 * SPAD];

    const int t = threadIdx.x;
    const int lane = t & 31, warp = t >> 5;
    const int wm = warp >> 2, wn = warp & 3;
    const int gid = lane >> 2, ctid = lane & 3;
    const int m0 = blockIdx.x * 64;
    const int n0 = blockIdx.y * 64;
    const int z  = blockIdx.z;

    const float* A = z ? X2 : X1;
    const int lrow = t >> 2;
    const int lc8  = (t & 3) * 8;
    const float* arow = A + (size_t)(m0 + lrow) * LDIM;
    const float* wrow = Wp + (size_t)(n0 + lrow) * (2 * LDIM) + z * LDIM;

    Frags F;
#pragma unroll
    for (int mf = 0; mf < 2; mf++)
#pragma unroll
        for (int nf = 0; nf < 2; nf++)
#pragma unroll
            for (int e = 0; e < 4; e++) F.acc[mf][nf][e] = 0.f;

    for (int kc = 0; kc < LDIM; kc += 32) {
        split_store(Ah, Al, lrow * SPAD + lc8,     *(const float4*)(arow + kc + lc8));
        split_store(Ah, Al, lrow * SPAD + lc8 + 4, *(const float4*)(arow + kc + lc8 + 4));
        split_store(Bh, Bl, lrow * SPAD + lc8,     *(const float4*)(wrow + kc + lc8));
        split_store(Bh, Bl, lrow * SPAD + lc8 + 4, *(const float4*)(wrow + kc + lc8 + 4));
        __syncthreads();
        mma_chunk(F, Ah, Al, Bh, Bl, wm, wn, gid, ctid);
        __syncthreads();
    }

    float* OUT = z ? S2P : S1;
#pragma unroll
    for (int mf = 0; mf < 2; mf++) {
        int row = m0 + wm * 32 + mf * 16 + gid;
#pragma unroll
        for (int nf = 0; nf < 2; nf++) {
            int col = n0 + wn * 16 + nf * 8 + 2 * ctid;
            float bv0 = z ? bp[col] : 0.f;
            float bv1 = z ? bp[col + 1] : 0.f;
            float v0 = F.acc[mf][nf][0] + bv0;
            float v1 = F.acc[mf][nf][1] + bv1;
            float v2 = F.acc[mf][nf][2] + bv0;
            float v3 = F.acc[mf][nf][3] + bv1;
            *(float2*)&OUT[(size_t)row * LDIM + col]       = make_float2(v0, v1);
            *(float2*)&OUT[(size_t)(row + 8) * LDIM + col] = make_float2(v2, v3);
        }
    }
}

// ---------------------------------------------------------------------------
// Fused pairwise + finalize (unchanged — known good).
// ---------------------------------------------------------------------------
#define SR2 65   // u64 per row (64 + 1 pad)
#define SM_S2   16640
#define SM_C1   24960
#define SM_C2   25024
#define SM_ROWF 50176
#define SM_U64_TOTAL 25280      // 202,240 bytes

__global__ __launch_bounds__(512)
void pairwise_final_kernel(const float* __restrict__ S1, const float* __restrict__ S2P,
                           const float* __restrict__ Wb, const float* __restrict__ bb,
                           const float* __restrict__ noise, float* __restrict__ out)
{
    extern __shared__ __align__(16) u64 sm[];
    u64*   s1t  = sm;
    u64*   s2t  = sm + SM_S2;
    u64*   c1   = sm + SM_C1;
    u64*   c2   = sm + SM_C2;
    float* rowA = ((float*)sm) + SM_ROWF;        // [4][64]
    float* rowB = rowA + 256;                    // [4][32]
    float* red  = (float*)sm;                    // aliased after main loop

    const int t  = threadIdx.x;
    const int b  = t >> 7;
    const int tb = t & 127;
    const int tx = tb & 7;
    const int ty = tb >> 3;
    const int i0 = blockIdx.y * 64;
    const int j0 = blockIdx.x * 32;

    if (t < 64) {
        float2 w = ((const float2*)Wb)[t];
        c1[t] = pack2(0.6f * w.x, 0.6f * w.y);
        c2[t] = pack2(0.4f * w.x, 0.4f * w.y);
    }

    const float4* S1v = (const float4*)S1;
    const float4* S2v = (const float4*)S2P;
#pragma unroll
    for (int s = 0; s < 16; s++) {
        int f   = t + s * 512;
        int bb_ = f >> 11;
        int rem = f & 2047;
        int row = rem >> 5;
        int c4  = rem & 31;
        float4 v = S1v[((size_t)bb_ * N_NODES + i0 + row) * 32 + c4];
        float2* d = (float2*)&s1t[(bb_ * 64 + row) * SR2 + c4 * 2];
        d[0] = make_float2(v.x, v.y);
        d[1] = make_float2(v.z, v.w);
    }
#pragma unroll
    for (int s = 0; s < 8; s++) {
        int f   = t + s * 512;
        int bb_ = f >> 10;
        int rem = f & 1023;
        int row = rem >> 5;
        int c4  = rem & 31;
        float4 v = S2v[((size_t)bb_ * N_NODES + j0 + row) * 32 + c4];
        float2* d = (float2*)&s2t[(bb_ * 32 + row) * SR2 + c4 * 2];
        d[0] = make_float2(v.x, v.y);
        d[1] = make_float2(v.z, v.w);
    }
    __syncthreads();

    if (t < 256) {
        const u64* src = s1t + t * SR2;
        u64 a0 = 0, a1 = 0;
#pragma unroll
        for (int q = 0; q < 64; q += 2) {
            a0 = fma2(c1[q],     src[q],     a0);
            a1 = fma2(c1[q + 1], src[q + 1], a1);
        }
        rowA[t] = lo32(a0) + hi32(a0) + lo32(a1) + hi32(a1);
    } else if (t < 384) {
        int r = t - 256;
        const u64* src = s2t + r * SR2;
        u64 a0 = 0, a1 = 0;
#pragma unroll
        for (int q = 0; q < 64; q += 2) {
            a0 = fma2(c1[q],     src[q],     a0);
            a1 = fma2(c1[q + 1], src[q + 1], a1);
        }
        rowB[r] = lo32(a0) + hi32(a0) + lo32(a1) + hi32(a1);
    }
    __syncthreads();

    u64 acc[4][4] = {};
    const u64 MASK = 0x7fffffff7fffffffULL;
    const u64* s1b = s1t + b * 64 * SR2;
    const u64* s2b = s2t + b * 32 * SR2;
#pragma unroll 2
    for (int kk = 0; kk < 64; kk++) {
        u64 cw = c2[kk];
        u64 ra[4], rb[4];
#pragma unroll
        for (int r = 0; r < 4; r++) ra[r] = s1b[(ty + 16 * r) * SR2 + kk];
#pragma unroll
        for (int c = 0; c < 4; c++) rb[c] = s2b[(tx + 8 * c) * SR2 + kk];
#pragma unroll
        for (int r = 0; r < 4; r++)
#pragma unroll
            for (int c = 0; c < 4; c++) {
                u64 v = add2(ra[r], rb[c]);
                acc[r][c] = fma2(cw, v & MASK, acc[r][c]);
            }
    }

    const float bbv = bb[0];
    float sig[4][4];
#pragma unroll
    for (int r = 0; r < 4; r++) {
        float ai = rowA[b * 64 + ty + 16 * r];
#pragma unroll
        for (int c = 0; c < 4; c++) {
            float z = lo32(acc[r][c]) + hi32(acc[r][c])
                    + ai + rowB[b * 32 + tx + 8 * c] + bbv;
            sig[r][c] = 1.f / (1.f + __expf(-z));
        }
    }
    __syncthreads();

#pragma unroll
    for (int r = 0; r < 4; r++)
#pragma unroll
        for (int c = 0; c < 4; c++)
            red[(b * 128 + tb) * 16 + r * 4 + c] = sig[r][c];
    __syncthreads();

#pragma unroll
    for (int e = 0; e < 4; e++) {
        int o = t * 4 + e;
        int i = o >> 5;
        int j = o & 31;
        int ty2 = i & 15, r2 = i >> 4;
        int tx2 = j & 7,  c2_ = j >> 3;
        int base = (ty2 * 8 + tx2) * 16 + r2 * 4 + c2_;
        float p = 0.25f * (red[base] + red[2048 + base]
                         + red[4096 + base] + red[6144 + base]);
        int gi = i0 + i, gj = j0 + j;
        if (gi == gj) p = 0.f;
        float lp = __logf(p + 1e-10f) - __logf(1.0f + (1e-10f - p));
        lp = fminf(fmaxf(lp, -10.f), 10.f);
        float ns = noise[(size_t)gi * N_NODES + gj];
        float lo = __logf(ns) - __logf(1.0f - ns);
        float z = (lp + lo) * 5.0f;
        out[(size_t)gi * N_NODES + gj] = 1.f / (1.f + __expf(-z));
    }
}

// ---------------------------------------------------------------------------
extern "C" void kernel_launch(void* const* d_in, const int* in_sizes, int n_in,
                              void* d_out, int out_size)
{
    const float* x     = (const float*)d_in[0];
    const float* W1    = (const float*)d_in[1];
    const float* b1    = (const float*)d_in[2];
    const float* W2    = (const float*)d_in[3];
    const float* b2    = (const float*)d_in[4];
    const float* Wp    = (const float*)d_in[5];
    const float* bp    = (const float*)d_in[6];
    const float* Wb    = (const float*)d_in[7];
    const float* bb    = (const float*)d_in[8];
    const float* noise = (const float*)d_in[9];
    float* out = (float*)d_out;

    float *X1, *X2, *S1, *S2P;
    cudaGetSymbolAddress((void**)&X1,  g_X1);
    cudaGetSymbolAddress((void**)&X2,  g_X2);
    cudaGetSymbolAddress((void**)&S1,  g_S1);
    cudaGetSymbolAddress((void**)&S2P, g_S2P);

    // Stage 1: [X1|X2] = leaky(x @ [W1;W2]^T + bias)   (3xTF32 mma)
    stage1_mma<<<dim3(MROWS / 64, 4), 256>>>(x, W1, W2, b1, b2, X1, X2);

    // Stage 2: S1 = X1@Wp_a^T, S2P = X2@Wp_b^T + bp    (3xTF32 mma)
    stage2_mma<<<dim3(MROWS / 64, 2, 2), 256>>>(X1, X2, Wp, bp, S1, S2P);

    // Stage 3: fused pairwise + finalize, writes out directly
    size_t smem = (size_t)SM_U64_TOTAL * sizeof(u64);
    cudaFuncSetAttribute(pairwise_final_kernel,
                         cudaFuncAttributeMaxDynamicSharedMemorySize, (int)smem);
    dim3 g3(N_NODES / 32, N_NODES / 64);   // 16 x 8 = 128 blocks
    pairwise_final_kernel<<<g3, dim3(512), smem>>>(S1, S2P, Wb, bb, noise, out);
}

// round 8
// speedup vs baseline: 1.2930x; 1.0059x over previous
#include <cuda_runtime.h>
#include <math.h>

#define N_NODES 512
#define TDIM 288
#define LDIM 128
#define BBATCH 4
#define MROWS (BBATCH * N_NODES)   // 2048

typedef unsigned long long u64;
typedef unsigned int u32;

// ---- packed f32x2 helpers (sm_100+) ----
__device__ __forceinline__ u64 add2(u64 a, u64 b) {
    u64 r; asm("add.rn.f32x2 %0,%1,%2;" : "=l"(r) : "l"(a), "l"(b)); return r;
}
__device__ __forceinline__ u64 fma2(u64 a, u64 b, u64 c) {
    u64 r; asm("fma.rn.f32x2 %0,%1,%2,%3;" : "=l"(r) : "l"(a), "l"(b), "l"(c)); return r;
}
__device__ __forceinline__ float lo32(u64 v) { return __uint_as_float((unsigned)(v & 0xffffffffu)); }
__device__ __forceinline__ float hi32(u64 v) { return __uint_as_float((unsigned)(v >> 32)); }
__device__ __forceinline__ u64 pack2(float x, float y) {
    return ((u64)__float_as_uint(y) << 32) | (u64)__float_as_uint(x);
}

// ---- tf32 helpers ----
__device__ __forceinline__ float to_tf32(float v) {
    u32 r; asm("cvt.rna.tf32.f32 %0,%1;" : "=r"(r) : "f"(v));
    return __uint_as_float(r);
}
__device__ __forceinline__ void mma_tf32(float* d, const u32* a, const u32* b) {
    asm("mma.sync.aligned.m16n8k8.row.col.f32.tf32.tf32.f32 "
        "{%0,%1,%2,%3}, {%4,%5,%6,%7}, {%8,%9}, {%0,%1,%2,%3};"
        : "+f"(d[0]), "+f"(d[1]), "+f"(d[2]), "+f"(d[3])
        : "r"(a[0]), "r"(a[1]), "r"(a[2]), "r"(a[3]), "r"(b[0]), "r"(b[1]));
}

// Scratch (device globals)
__device__ float g_X1[MROWS * LDIM];
__device__ float g_X2[MROWS * LDIM];
__device__ float g_S1[MROWS * LDIM];
__device__ float g_S2P[MROWS * LDIM];

// ---------------------------------------------------------------------------
// 3xTF32 mma GEMM core. Tile BM=32, BN=64, BK=32. 256 threads = 8 warps
// (2 m-warps x 4 n-warps, each 16m x 16n = 1 mfrag x 2 nfrag).
// Double-buffered DYNAMIC smem, 2-deep register prefetch, 1 barrier/chunk.
// ---------------------------------------------------------------------------
#define SPAD 36
// dynamic smem layout (floats):
#define GA_SZ (32 * SPAD)          // one A buffer (hi or lo)
#define GB_SZ (64 * SPAD)
#define OFF_AH(buf) ((buf) * GA_SZ)
#define OFF_AL(buf) (2 * GA_SZ + (buf) * GA_SZ)
#define OFF_BH(buf) (4 * GA_SZ + (buf) * GB_SZ)
#define OFF_BL(buf) (4 * GA_SZ + 2 * GB_SZ + (buf) * GB_SZ)
#define GEMM_SMEM_FLOATS (4 * GA_SZ + 4 * GB_SZ)   // 13824 floats = 55296 B

__device__ __forceinline__ void split_store(float* H, float* L, int idx4, float4 v) {
    float4 h, l;
    h.x = to_tf32(v.x); l.x = to_tf32(v.x - h.x);
    h.y = to_tf32(v.y); l.y = to_tf32(v.y - h.y);
    h.z = to_tf32(v.z); l.z = to_tf32(v.z - h.z);
    h.w = to_tf32(v.w); l.w = to_tf32(v.w - h.w);
    *(float4*)(H + idx4) = h;
    *(float4*)(L + idx4) = l;
}

// mma over one 32-K chunk for this warp (1 mfrag x 2 nfrag, 3xTF32).
__device__ __forceinline__ void mma_chunk32(float acc[2][4],
                                            const float* Ah, const float* Al,
                                            const float* Bh, const float* Bl,
                                            int wm, int wn, int gid, int ctid) {
    const u32* AhU = (const u32*)Ah; const u32* AlU = (const u32*)Al;
    const u32* BhU = (const u32*)Bh; const u32* BlU = (const u32*)Bl;
    const int ar0 = (wm * 16 + gid) * SPAD;
    const int ar1 = (wm * 16 + gid + 8) * SPAD;
#pragma unroll
    for (int kk = 0; kk < 4; kk++) {
        int k8 = kk * 8;
        u32 ah[4], al[4], bh[2][2], bl[2][2];
        ah[0] = AhU[ar0 + k8 + ctid];     ah[1] = AhU[ar1 + k8 + ctid];
        ah[2] = AhU[ar0 + k8 + ctid + 4]; ah[3] = AhU[ar1 + k8 + ctid + 4];
        al[0] = AlU[ar0 + k8 + ctid];     al[1] = AlU[ar1 + k8 + ctid];
        al[2] = AlU[ar0 + k8 + ctid + 4]; al[3] = AlU[ar1 + k8 + ctid + 4];
#pragma unroll
        for (int nf = 0; nf < 2; nf++) {
            int r = (wn * 16 + nf * 8 + gid) * SPAD;
            bh[nf][0] = BhU[r + k8 + ctid];
            bh[nf][1] = BhU[r + k8 + ctid + 4];
            bl[nf][0] = BlU[r + k8 + ctid];
            bl[nf][1] = BlU[r + k8 + ctid + 4];
        }
#pragma unroll
        for (int nf = 0; nf < 2; nf++) {
            mma_tf32(acc[nf], ah, bh[nf]);
            mma_tf32(acc[nf], ah, bl[nf]);
            mma_tf32(acc[nf], al, bh[nf]);
        }
    }
}

// ---------------------------------------------------------------------------
// Stage 1: [X1|X2](2048 x 256) = leaky(x(2048x288) @ [W1;W2]^T + [b1;b2])
// grid (64, 4) = 256 blocks.
// ---------------------------------------------------------------------------
__global__ __launch_bounds__(256)
void stage1_mma(const float* __restrict__ x,
                const float* __restrict__ W1, const float* __restrict__ W2,
                const float* __restrict__ b1, const float* __restrict__ b2,
                float* __restrict__ X1, float* __restrict__ X2)
{
    extern __shared__ __align__(16) float gsm[];

    const int t = threadIdx.x;
    const int lane = t & 31, warp = t >> 5;
    const int wm = warp >> 2, wn = warp & 3;
    const int gid = lane >> 2, ctid = lane & 3;
    const int m0 = blockIdx.x * 32;
    const int n0 = blockIdx.y * 64;

    const int arI = t >> 3;          // A row 0..31
    const int ak  = (t & 7) * 4;     // A col (floats)
    const int brI = t >> 2;          // B row 0..63
    const int bk  = (t & 3) * 8;     // B col (floats)

    const float* arow = x + (size_t)(m0 + arI) * TDIM + ak;
    const float* wrow = (n0 + brI) < 128
        ? W1 + (size_t)(n0 + brI) * TDIM + bk
        : W2 + (size_t)(n0 + brI - 128) * TDIM + bk;

    float acc[2][4] = {};
    const int nt = TDIM / 32;        // 9

    float4 rA, rB0, rB1;
    rA  = *(const float4*)(arow);
    rB0 = *(const float4*)(wrow);
    rB1 = *(const float4*)(wrow + 4);
    split_store(gsm + OFF_AH(0), gsm + OFF_AL(0), arI * SPAD + ak, rA);
    split_store(gsm + OFF_BH(0), gsm + OFF_BL(0), brI * SPAD + bk, rB0);
    split_store(gsm + OFF_BH(0), gsm + OFF_BL(0), brI * SPAD + bk + 4, rB1);
    rA  = *(const float4*)(arow + 32);
    rB0 = *(const float4*)(wrow + 32);
    rB1 = *(const float4*)(wrow + 36);
    __syncthreads();

    for (int ti = 0; ti < nt; ti++) {
        int cur = ti & 1;
        if (ti + 1 < nt) {
            int nx = cur ^ 1;
            split_store(gsm + OFF_AH(nx), gsm + OFF_AL(nx), arI * SPAD + ak, rA);
            split_store(gsm + OFF_BH(nx), gsm + OFF_BL(nx), brI * SPAD + bk, rB0);
            split_store(gsm + OFF_BH(nx), gsm + OFF_BL(nx), brI * SPAD + bk + 4, rB1);
            if (ti + 2 < nt) {
                int k0 = (ti + 2) * 32;
                rA  = *(const float4*)(arow + k0);
                rB0 = *(const float4*)(wrow + k0);
                rB1 = *(const float4*)(wrow + k0 + 4);
            }
        }
        mma_chunk32(acc, gsm + OFF_AH(cur), gsm + OFF_AL(cur),
                    gsm + OFF_BH(cur), gsm + OFF_BL(cur), wm, wn, gid, ctid);
        __syncthreads();
    }

    const int half = (n0 < 128);
    float* OUT = half ? X1 : X2;
    const float* bias = half ? b1 : b2;
    const int nloc0 = half ? n0 : n0 - 128;
    const int row = m0 + wm * 16 + gid;
#pragma unroll
    for (int nf = 0; nf < 2; nf++) {
        int col = nloc0 + wn * 16 + nf * 8 + 2 * ctid;
        float v0 = acc[nf][0] + bias[col];
        float v1 = acc[nf][1] + bias[col + 1];
        float v2 = acc[nf][2] + bias[col];
        float v3 = acc[nf][3] + bias[col + 1];
        v0 = fmaxf(v0, 0.2f * v0); v1 = fmaxf(v1, 0.2f * v1);
        v2 = fmaxf(v2, 0.2f * v2); v3 = fmaxf(v3, 0.2f * v3);
        *(float2*)&OUT[(size_t)row * LDIM + col]       = make_float2(v0, v1);
        *(float2*)&OUT[(size_t)(row + 8) * LDIM + col] = make_float2(v2, v3);
    }
}

// ---------------------------------------------------------------------------
// Stage 2: z=0: S1 = X1 @ Wp[:, :128]^T ;  z=1: S2P = X2 @ Wp[:,128:]^T + bp
// grid (64, 2, 2) = 256 blocks.
// ---------------------------------------------------------------------------
__global__ __launch_bounds__(256)
void stage2_mma(const float* __restrict__ X1, const float* __restrict__ X2,
                const float* __restrict__ Wp, const float* __restrict__ bp,
                float* __restrict__ S1, float* __restrict__ S2P)
{
    extern __shared__ __align__(16) float gsm[];

    const int t = threadIdx.x;
    const int lane = t & 31, warp = t >> 5;
    const int wm = warp >> 2, wn = warp & 3;
    const int gid = lane >> 2, ctid = lane & 3;
    const int m0 = blockIdx.x * 32;
    const int n0 = blockIdx.y * 64;
    const int z  = blockIdx.z;

    const float* A = z ? X2 : X1;
    const int arI = t >> 3;
    const int ak  = (t & 7) * 4;
    const int brI = t >> 2;
    const int bk  = (t & 3) * 8;
    const float* arow = A + (size_t)(m0 + arI) * LDIM + ak;
    const float* wrow = Wp + (size_t)(n0 + brI) * (2 * LDIM) + z * LDIM + bk;

    float acc[2][4] = {};
    const int nt = LDIM / 32;        // 4

    float4 rA, rB0, rB1;
    rA  = *(const float4*)(arow);
    rB0 = *(const float4*)(wrow);
    rB1 = *(const float4*)(wrow + 4);
    split_store(gsm + OFF_AH(0), gsm + OFF_AL(0), arI * SPAD + ak, rA);
    split_store(gsm + OFF_BH(0), gsm + OFF_BL(0), brI * SPAD + bk, rB0);
    split_store(gsm + OFF_BH(0), gsm + OFF_BL(0), brI * SPAD + bk + 4, rB1);
    rA  = *(const float4*)(arow + 32);
    rB0 = *(const float4*)(wrow + 32);
    rB1 = *(const float4*)(wrow + 36);
    __syncthreads();

    for (int ti = 0; ti < nt; ti++) {
        int cur = ti & 1;
        if (ti + 1 < nt) {
            int nx = cur ^ 1;
            split_store(gsm + OFF_AH(nx), gsm + OFF_AL(nx), arI * SPAD + ak, rA);
            split_store(gsm + OFF_BH(nx), gsm + OFF_BL(nx), brI * SPAD + bk, rB0);
            split_store(gsm + OFF_BH(nx), gsm + OFF_BL(nx), brI * SPAD + bk + 4, rB1);
            if (ti + 2 < nt) {
                int k0 = (ti + 2) * 32;
                rA  = *(const float4*)(arow + k0);
                rB0 = *(const float4*)(wrow + k0);
                rB1 = *(const float4*)(wrow + k0 + 4);
            }
        }
        mma_chunk32(acc, gsm + OFF_AH(cur), gsm + OFF_AL(cur),
                    gsm + OFF_BH(cur), gsm + OFF_BL(cur), wm, wn, gid, ctid);
        __syncthreads();
    }

    float* OUT = z ? S2P : S1;
    const int row = m0 + wm * 16 + gid;
#pragma unroll
    for (int nf = 0; nf < 2; nf++) {
        int col = n0 + wn * 16 + nf * 8 + 2 * ctid;
        float bv0 = z ? bp[col] : 0.f;
        float bv1 = z ? bp[col + 1] : 0.f;
        float v0 = acc[nf][0] + bv0;
        float v1 = acc[nf][1] + bv1;
        float v2 = acc[nf][2] + bv0;
        float v3 = acc[nf][3] + bv1;
        *(float2*)&OUT[(size_t)row * LDIM + col]       = make_float2(v0, v1);
        *(float2*)&OUT[(size_t)(row + 8) * LDIM + col] = make_float2(v2, v3);
    }
}

// ---------------------------------------------------------------------------
// Fused pairwise + finalize (unchanged — known good).
// ---------------------------------------------------------------------------
#define SR2 65   // u64 per row (64 + 1 pad)
#define SM_S2   16640
#define SM_C1   24960
#define SM_C2   25024
#define SM_ROWF 50176
#define SM_U64_TOTAL 25280      // 202,240 bytes

__global__ __launch_bounds__(512)
void pairwise_final_kernel(const float* __restrict__ S1, const float* __restrict__ S2P,
                           const float* __restrict__ Wb, const float* __restrict__ bb,
                           const float* __restrict__ noise, float* __restrict__ out)
{
    extern __shared__ __align__(16) u64 sm[];
    u64*   s1t  = sm;
    u64*   s2t  = sm + SM_S2;
    u64*   c1   = sm + SM_C1;
    u64*   c2   = sm + SM_C2;
    float* rowA = ((float*)sm) + SM_ROWF;        // [4][64]
    float* rowB = rowA + 256;                    // [4][32]
    float* red  = (float*)sm;                    // aliased after main loop

    const int t  = threadIdx.x;
    const int b  = t >> 7;
    const int tb = t & 127;
    const int tx = tb & 7;
    const int ty = tb >> 3;
    const int i0 = blockIdx.y * 64;
    const int j0 = blockIdx.x * 32;

    if (t < 64) {
        float2 w = ((const float2*)Wb)[t];
        c1[t] = pack2(0.6f * w.x, 0.6f * w.y);
        c2[t] = pack2(0.4f * w.x, 0.4f * w.y);
    }

    const float4* S1v = (const float4*)S1;
    const float4* S2v = (const float4*)S2P;
#pragma unroll
    for (int s = 0; s < 16; s++) {
        int f   = t + s * 512;
        int bb_ = f >> 11;
        int rem = f & 2047;
        int row = rem >> 5;
        int c4  = rem & 31;
        float4 v = S1v[((size_t)bb_ * N_NODES + i0 + row) * 32 + c4];
        float2* d = (float2*)&s1t[(bb_ * 64 + row) * SR2 + c4 * 2];
        d[0] = make_float2(v.x, v.y);
        d[1] = make_float2(v.z, v.w);
    }
#pragma unroll
    for (int s = 0; s < 8; s++) {
        int f   = t + s * 512;
        int bb_ = f >> 10;
        int rem = f & 1023;
        int row = rem >> 5;
        int c4  = rem & 31;
        float4 v = S2v[((size_t)bb_ * N_NODES + j0 + row) * 32 + c4];
        float2* d = (float2*)&s2t[(bb_ * 32 + row) * SR2 + c4 * 2];
        d[0] = make_float2(v.x, v.y);
        d[1] = make_float2(v.z, v.w);
    }
    __syncthreads();

    if (t < 256) {
        const u64* src = s1t + t * SR2;
        u64 a0 = 0, a1 = 0;
#pragma unroll
        for (int q = 0; q < 64; q += 2) {
            a0 = fma2(c1[q],     src[q],     a0);
            a1 = fma2(c1[q + 1], src[q + 1], a1);
        }
        rowA[t] = lo32(a0) + hi32(a0) + lo32(a1) + hi32(a1);
    } else if (t < 384) {
        int r = t - 256;
        const u64* src = s2t + r * SR2;
        u64 a0 = 0, a1 = 0;
#pragma unroll
        for (int q = 0; q < 64; q += 2) {
            a0 = fma2(c1[q],     src[q],     a0);
            a1 = fma2(c1[q + 1], src[q + 1], a1);
        }
        rowB[r] = lo32(a0) + hi32(a0) + lo32(a1) + hi32(a1);
    }
    __syncthreads();

    u64 acc[4][4] = {};
    const u64 MASK = 0x7fffffff7fffffffULL;
    const u64* s1b = s1t + b * 64 * SR2;
    const u64* s2b = s2t + b * 32 * SR2;
#pragma unroll 2
    for (int kk = 0; kk < 64; kk++) {
        u64 cw = c2[kk];
        u64 ra[4], rb[4];
#pragma unroll
        for (int r = 0; r < 4; r++) ra[r] = s1b[(ty + 16 * r) * SR2 + kk];
#pragma unroll
        for (int c = 0; c < 4; c++) rb[c] = s2b[(tx + 8 * c) * SR2 + kk];
#pragma unroll
        for (int r = 0; r < 4; r++)
#pragma unroll
            for (int c = 0; c < 4; c++) {
                u64 v = add2(ra[r], rb[c]);
                acc[r][c] = fma2(cw, v & MASK, acc[r][c]);
            }
    }

    const float bbv = bb[0];
    float sig[4][4];
#pragma unroll
    for (int r = 0; r < 4; r++) {
        float ai = rowA[b * 64 + ty + 16 * r];
#pragma unroll
        for (int c = 0; c < 4; c++) {
            float z = lo32(acc[r][c]) + hi32(acc[r][c])
                    + ai + rowB[b * 32 + tx + 8 * c] + bbv;
            sig[r][c] = 1.f / (1.f + __expf(-z));
        }
    }
    __syncthreads();

#pragma unroll
    for (int r = 0; r < 4; r++)
#pragma unroll
        for (int c = 0; c < 4; c++)
            red[(b * 128 + tb) * 16 + r * 4 + c] = sig[r][c];
    __syncthreads();

#pragma unroll
    for (int e = 0; e < 4; e++) {
        int o = t * 4 + e;
        int i = o >> 5;
        int j = o & 31;
        int ty2 = i & 15, r2 = i >> 4;
        int tx2 = j & 7,  c2_ = j >> 3;
        int base = (ty2 * 8 + tx2) * 16 + r2 * 4 + c2_;
        float p = 0.25f * (red[base] + red[2048 + base]
                         + red[4096 + base] + red[6144 + base]);
        int gi = i0 + i, gj = j0 + j;
        if (gi == gj) p = 0.f;
        float lp = __logf(p + 1e-10f) - __logf(1.0f + (1e-10f - p));
        lp = fminf(fmaxf(lp, -10.f), 10.f);
        float ns = noise[(size_t)gi * N_NODES + gj];
        float lo = __logf(ns) - __logf(1.0f - ns);
        float z = (lp + lo) * 5.0f;
        out[(size_t)gi * N_NODES + gj] = 1.f / (1.f + __expf(-z));
    }
}

// ---------------------------------------------------------------------------
extern "C" void kernel_launch(void* const* d_in, const int* in_sizes, int n_in,
                              void* d_out, int out_size)
{
    const float* x     = (const float*)d_in[0];
    const float* W1    = (const float*)d_in[1];
    const float* b1    = (const float*)d_in[2];
    const float* W2    = (const float*)d_in[3];
    const float* b2    = (const float*)d_in[4];
    const float* Wp    = (const float*)d_in[5];
    const float* bp    = (const float*)d_in[6];
    const float* Wb    = (const float*)d_in[7];
    const float* bb    = (const float*)d_in[8];
    const float* noise = (const float*)d_in[9];
    float* out = (float*)d_out;

    float *X1, *X2, *S1, *S2P;
    cudaGetSymbolAddress((void**)&X1,  g_X1);
    cudaGetSymbolAddress((void**)&X2,  g_X2);
    cudaGetSymbolAddress((void**)&S1,  g_S1);
    cudaGetSymbolAddress((void**)&S2P, g_S2P);

    const size_t gemm_smem = (size_t)GEMM_SMEM_FLOATS * sizeof(float);  // 55296 B
    cudaFuncSetAttribute(stage1_mma, cudaFuncAttributeMaxDynamicSharedMemorySize,
                         (int)gemm_smem);
    cudaFuncSetAttribute(stage2_mma, cudaFuncAttributeMaxDynamicSharedMemorySize,
                         (int)gemm_smem);

    // Stage 1: [X1|X2] = leaky(x @ [W1;W2]^T + bias)   (3xTF32 mma)
    stage1_mma<<<dim3(MROWS / 32, 4), 256, gemm_smem>>>(x, W1, W2, b1, b2, X1, X2);

    // Stage 2: S1 = X1@Wp_a^T, S2P = X2@Wp_b^T + bp    (3xTF32 mma)
    stage2_mma<<<dim3(MROWS / 32, 2, 2), 256, gemm_smem>>>(X1, X2, Wp, bp, S1, S2P);

    // Stage 3: fused pairwise + finalize, writes out directly
    size_t smem = (size_t)SM_U64_TOTAL * sizeof(u64);
    cudaFuncSetAttribute(pairwise_final_kernel,
                         cudaFuncAttributeMaxDynamicSharedMemorySize, (int)smem);
    dim3 g3(N_NODES / 32, N_NODES / 64);   // 16 x 8 = 128 blocks
    pairwise_final_kernel<<<g3, dim3(512), smem>>>(S1, S2P, Wb, bb, noise, out);
}